// round 2
// baseline (speedup 1.0000x reference)
#include <cuda_runtime.h>
#include <math.h>

// DSimilarity gradgrad: out[ia*3+a, jb*3+b] =
//   sum_{p: i1[p]=ia} sum_{q: i2[q]=jb} gg(d1_p, d2_q) * u1[p,a] * u2[q,b]
// gg(x,y) = (inv_l2 - (x-y)^2*inv_l2^2) * exp(-0.5*(x-y)^2*inv_l2)
//
// Strategy: CSR-group pairs by atom index (deterministic order), then one
// thread per (ia, jb) output 3x3 block. No atomics in the hot path; every
// output element written exactly once. exp computed with FMA-only polynomial
// to avoid the MUFU throughput ceiling.

#define MAXP 16384
#define MAXA 4096

__device__ float4 g_s1[MAXP];          // (d1, u1x*invl2, u1y*invl2, u1z*invl2) sorted by atom
__device__ float4 g_s2[MAXP];          // (d2, u2x, u2y, u2z) sorted by atom
__device__ int    g_off1[MAXA + 1], g_off2[MAXA + 1];
__device__ int    g_cnt1[MAXA],     g_cnt2[MAXA];
__device__ int    g_cur1[MAXA],     g_cur2[MAXA];
__device__ int    g_idx1[MAXP],     g_idx2[MAXP];

// ---------------------------------------------------------------- preprocessing

__global__ void k_zero(int na1, int na2) {
    int t = blockIdx.x * blockDim.x + threadIdx.x;
    if (t < na1) g_cnt1[t] = 0;
    if (t < na2) g_cnt2[t] = 0;
}

__global__ void k_hist(const int* __restrict__ i1, const int* __restrict__ i2,
                       int n1, int n2) {
    int t = blockIdx.x * blockDim.x + threadIdx.x;
    if (t < n1) atomicAdd(&g_cnt1[i1[t]], 1);
    if (t < n2) atomicAdd(&g_cnt2[i2[t]], 1);
}

// one warp per side: chunked inclusive warp-scan over counts
__global__ void k_scan(int na1, int na2) {
    int w    = threadIdx.x >> 5;
    int lane = threadIdx.x & 31;
    if (w > 1) return;
    int  na  = w ? na2 : na1;
    int* cnt = w ? g_cnt2 : g_cnt1;
    int* off = w ? g_off2 : g_off1;
    int* cur = w ? g_cur2 : g_cur1;
    int run = 0;
    for (int base = 0; base < na; base += 32) {
        int i = base + lane;
        int c = (i < na) ? cnt[i] : 0;
        int s = c;
        #pragma unroll
        for (int d = 1; d < 32; d <<= 1) {
            int t = __shfl_up_sync(0xFFFFFFFFu, s, d);
            if (lane >= d) s += t;
        }
        int excl = run + s - c;
        if (i < na) { off[i] = excl; cur[i] = excl; }
        run += __shfl_sync(0xFFFFFFFFu, s, 31);
    }
    if (lane == 0) off[na] = run;
}

__global__ void k_scatter(const int* __restrict__ i1, const int* __restrict__ i2,
                          int n1, int n2) {
    int t = blockIdx.x * blockDim.x + threadIdx.x;
    if (t < n1) { int pos = atomicAdd(&g_cur1[i1[t]], 1); g_idx1[pos] = t; }
    if (t < n2) { int pos = atomicAdd(&g_cur2[i2[t]], 1); g_idx2[pos] = t; }
}

// per-atom insertion sort of original indices -> deterministic accumulation order
__global__ void k_sortgroups(int na1, int na2) {
    int t = blockIdx.x * blockDim.x + threadIdx.x;
    int* buf; int lo, hi;
    if (t < na1)              { buf = g_idx1; lo = g_off1[t]; hi = g_off1[t + 1]; }
    else if (t < na1 + na2)   { int a = t - na1; buf = g_idx2; lo = g_off2[a]; hi = g_off2[a + 1]; }
    else return;
    for (int i = lo + 1; i < hi; i++) {
        int v = buf[i];
        int j = i - 1;
        while (j >= lo && buf[j] > v) { buf[j + 1] = buf[j]; j--; }
        buf[j + 1] = v;
    }
}

__global__ void k_gather(const float* __restrict__ d1, const float* __restrict__ u1,
                         const float* __restrict__ d2, const float* __restrict__ u2,
                         const float* __restrict__ ls, int n1, int n2) {
    int t = blockIdx.x * blockDim.x + threadIdx.x;
    float l = ls[0];
    float invl2 = 1.0f / (l * l);
    if (t < n1) {
        int p = g_idx1[t];
        g_s1[t] = make_float4(d1[p], u1[3 * p] * invl2, u1[3 * p + 1] * invl2,
                              u1[3 * p + 2] * invl2);
    }
    if (t < n2) {
        int q = g_idx2[t];
        g_s2[t] = make_float4(d2[q], u2[3 * q], u2[3 * q + 1], u2[3 * q + 2]);
    }
}

// ---------------------------------------------------------------- main compute
// fast exp2-style: computes exp(w*d2v) with w*log2(e) prefolded into wl2e.
// FMA-only, rel err ~1e-7, valid for result in normal range (always true here:
// d2v <= 25, invl2 = 1 -> exponent >= -19).

__global__ void k_main(float* __restrict__ out, int na1, int na2,
                       const float* __restrict__ ls) {
    int idx = blockIdx.x * blockDim.x + threadIdx.x;
    if (idx >= na1 * na2) return;
    int ia = idx / na2;
    int jb = idx - ia * na2;

    const float l = ls[0];
    const float invl2 = 1.0f / (l * l);
    const float wl2e  = -0.5f * invl2 * 1.4426950408889634f;  // -0.5*invl2*log2(e)
    const float MAGIC = 12582912.0f;                          // 1.5 * 2^23

    const int p0 = g_off1[ia], p1 = g_off1[ia + 1];
    const int q0 = g_off2[jb], q1 = g_off2[jb + 1];

    float a00 = 0.f, a01 = 0.f, a02 = 0.f;
    float a10 = 0.f, a11 = 0.f, a12 = 0.f;
    float a20 = 0.f, a21 = 0.f, a22 = 0.f;

    for (int p = p0; p < p1; p++) {
        const float4 P = g_s1[p];              // uniform across warp (same ia)
        for (int q = q0; q < q1; q++) {
            const float4 Q = g_s2[q];
            float diff = P.x - Q.x;
            float d2v  = diff * diff;
            // k = exp(-0.5*invl2*d2v) = 2^(wl2e*d2v)
            float t = fmaf(d2v, wl2e, MAGIC);      // round fixed-point
            float n = t - MAGIC;                   // integer part of exponent
            float f = fmaf(d2v, wl2e, -n);         // frac in [-0.5, 0.5]
            float pp =              1.5403530393e-4f;
            pp = fmaf(pp, f, 1.3333558146e-3f);
            pp = fmaf(pp, f, 9.6181291076e-3f);
            pp = fmaf(pp, f, 5.5504108665e-2f);
            pp = fmaf(pp, f, 2.4022650696e-1f);
            pp = fmaf(pp, f, 6.9314718056e-1f);
            pp = fmaf(pp, f, 1.0f);
            int ei = __float_as_int(t) - 0x4B400000;               // (int)n
            float k = __int_as_float(__float_as_int(pp) + (ei << 23));
            float g = fmaf(d2v, -invl2, 1.0f) * k; // (1 - d2v*invl2)*k; invl2 factor is in P.yzw
            float b0 = g * Q.y, b1 = g * Q.z, b2 = g * Q.w;
            a00 = fmaf(P.y, b0, a00); a01 = fmaf(P.y, b1, a01); a02 = fmaf(P.y, b2, a02);
            a10 = fmaf(P.z, b0, a10); a11 = fmaf(P.z, b1, a11); a12 = fmaf(P.z, b2, a12);
            a20 = fmaf(P.w, b0, a20); a21 = fmaf(P.w, b1, a21); a22 = fmaf(P.w, b2, a22);
        }
    }

    const int ld = na2 * 3;
    float* o = out + (ia * 3) * ld + jb * 3;
    o[0] = a00; o[1] = a01; o[2] = a02; o += ld;
    o[0] = a10; o[1] = a11; o[2] = a12; o += ld;
    o[0] = a20; o[1] = a21; o[2] = a22;
}

// ---------------------------------------------------------------- launch

extern "C" void kernel_launch(void* const* d_in, const int* in_sizes, int n_in,
                              void* d_out, int out_size) {
    const float* d1 = (const float*)d_in[0];
    const float* u1 = (const float*)d_in[1];
    const float* d2 = (const float*)d_in[2];
    const float* u2 = (const float*)d_in[3];
    const float* ls = (const float*)d_in[4];
    const int*   i1 = (const int*)d_in[5];
    const int*   i2 = (const int*)d_in[6];
    float* out = (float*)d_out;

    int n1 = in_sizes[0];                 // npairs side 1 (d1 is [n,1])
    int n2 = in_sizes[2];                 // npairs side 2
    // out is [na1*3, na2*3]; problem has na1 == na2
    int side = (int)(sqrt((double)out_size) + 0.5);
    int na1 = side / 3;
    int na2 = side / 3;

    int nmax = n1 > n2 ? n1 : n2;
    int namax = na1 > na2 ? na1 : na2;

    k_zero<<<(namax + 255) / 256, 256>>>(na1, na2);
    k_hist<<<(nmax + 255) / 256, 256>>>(i1, i2, n1, n2);
    k_scan<<<1, 64>>>(na1, na2);
    k_scatter<<<(nmax + 255) / 256, 256>>>(i1, i2, n1, n2);
    k_sortgroups<<<(na1 + na2 + 255) / 256, 256>>>(na1, na2);
    k_gather<<<(nmax + 255) / 256, 256>>>(d1, u1, d2, u2, ls, n1, n2);

    int total = na1 * na2;
    k_main<<<(total + 255) / 256, 256>>>(out, na1, na2, ls);
}

// round 3
// speedup vs baseline: 1.0445x; 1.0445x over previous
#include <cuda_runtime.h>
#include <math.h>

// DSimilarity gradgrad: out[ia*3+a, jb*3+b] =
//   sum_{p: i1[p]=ia} sum_{q: i2[q]=jb} gg(d1_p, d2_q) * u1[p,a] * u2[q,b]
// gg(x,y) = (inv_l2 - (x-y)^2*inv_l2^2) * exp(-0.5*(x-y)^2*inv_l2)
//
// v3: single fused preprocessing kernel (1 block) + compute kernel with
//  - jb slots sorted by group size (stable counting sort) -> warp lanes have
//    near-equal inner trip counts (kills lane-max divergence)
//  - s2 stored in slot order -> per-block contiguous range staged into SMEM
//    (inner loads become LDS instead of scattered-LDG wavefronts)
//  - __expf (MUFU pipe) overlapping the FMA pipe

#define MAXP   16384
#define MAXA   1024      // atoms per side (problem: 500)
#define MAXCNT 64        // count buckets for slot sort
#define PAIR_CAP 128     // staged pairs per block (per-atom count ~25 max)

__device__ float4 g_s1[MAXP];        // (d1, u1x*invl2, u1y*invl2, u1z*invl2), atom-sorted
__device__ float4 g_s2p[MAXP];       // (d2, u2x, u2y, u2z), SLOT-sorted
__device__ int    g_off1[MAXA + 1];
__device__ int    g_off2p[MAXA + 1]; // per-slot offsets into g_s2p
__device__ int    g_jperm[MAXA];     // slot -> jb
__device__ int    g_idx1[MAXP], g_idx2[MAXP], g_idx2p[MAXP];

// ------------------------------------------------------------------ fused prep
// ONE block, 1024 threads. All sizing: na<=1024, n<=16384.
__global__ void k_prep(const float* __restrict__ d1, const float* __restrict__ u1,
                       const float* __restrict__ d2, const float* __restrict__ u2,
                       const float* __restrict__ ls,
                       const int* __restrict__ i1, const int* __restrict__ i2,
                       int n1, int n2, int na1, int na2) {
    __shared__ int sc1[MAXA], sc2[MAXA];
    __shared__ int so1[MAXA + 1], so2[MAXA + 1];
    __shared__ int scur1[MAXA], scur2[MAXA];
    __shared__ int so2p[MAXA + 1];
    __shared__ int bucket[MAXCNT], bbase[MAXCNT];

    const int tid = threadIdx.x;
    const int nthr = blockDim.x;
    const int lane = tid & 31;
    const int warp = tid >> 5;

    // 1. zero counts
    for (int t = tid; t < na1; t += nthr) sc1[t] = 0;
    for (int t = tid; t < na2; t += nthr) sc2[t] = 0;
    if (tid < MAXCNT) bucket[tid] = 0;
    __syncthreads();

    // 2. histogram
    for (int t = tid; t < n1; t += nthr) atomicAdd(&sc1[i1[t]], 1);
    for (int t = tid; t < n2; t += nthr) atomicAdd(&sc2[i2[t]], 1);
    __syncthreads();

    // 3. exclusive scans (warp 0 -> side1, warp 1 -> side2)
    if (warp < 2) {
        int  na  = warp ? na2 : na1;
        int* cnt = warp ? sc2 : sc1;
        int* off = warp ? so2 : so1;
        int run = 0;
        for (int base = 0; base < na; base += 32) {
            int i = base + lane;
            int c = (i < na) ? cnt[i] : 0;
            int s = c;
            #pragma unroll
            for (int d = 1; d < 32; d <<= 1) {
                int t = __shfl_up_sync(0xFFFFFFFFu, s, d);
                if (lane >= d) s += t;
            }
            if (i < na) off[i] = run + s - c;
            run += __shfl_sync(0xFFFFFFFFu, s, 31);
        }
        if (lane == 0) off[na] = run;
    }
    __syncthreads();

    // 4. copy cursors, then scatter
    for (int t = tid; t < na1; t += nthr) scur1[t] = so1[t];
    for (int t = tid; t < na2; t += nthr) scur2[t] = so2[t];
    __syncthreads();
    for (int t = tid; t < n1; t += nthr) { int pos = atomicAdd(&scur1[i1[t]], 1); g_idx1[pos] = t; }
    for (int t = tid; t < n2; t += nthr) { int pos = atomicAdd(&scur2[i2[t]], 1); g_idx2[pos] = t; }
    __syncthreads();

    // 5. per-group insertion sort -> deterministic accumulation order
    for (int t = tid; t < na1 + na2; t += nthr) {
        int* buf; int lo, hi;
        if (t < na1) { buf = g_idx1; lo = so1[t]; hi = so1[t + 1]; }
        else         { int a = t - na1; buf = g_idx2; lo = so2[a]; hi = so2[a + 1]; }
        for (int i = lo + 1; i < hi; i++) {
            int v = buf[i];
            int j = i - 1;
            while (j >= lo && buf[j] > v) { buf[j + 1] = buf[j]; j--; }
            buf[j + 1] = v;
        }
    }
    __syncthreads();

    // 6. slot permutation: stable counting sort of jb by group count
    for (int t = tid; t < na2; t += nthr) atomicAdd(&bucket[min(sc2[t], MAXCNT - 1)], 1);
    __syncthreads();
    if (tid == 0) {
        int run = 0;
        for (int c = 0; c < MAXCNT; c++) { bbase[c] = run; run += bucket[c]; }
    }
    __syncthreads();
    for (int jb = tid; jb < na2; jb += nthr) {
        int c = min(sc2[jb], MAXCNT - 1);
        int r = bbase[c];
        for (int j = 0; j < jb; j++) r += (min(sc2[j], MAXCNT - 1) == c);
        g_jperm[r] = jb;
    }
    __syncthreads();

    // 7. scan per-slot counts -> g_off2p (warp 0)
    if (warp == 0) {
        int run = 0;
        for (int base = 0; base < na2; base += 32) {
            int i = base + lane;
            int c = (i < na2) ? sc2[g_jperm[i]] : 0;
            int s = c;
            #pragma unroll
            for (int d = 1; d < 32; d <<= 1) {
                int t = __shfl_up_sync(0xFFFFFFFFu, s, d);
                if (lane >= d) s += t;
            }
            if (i < na2) so2p[i] = run + s - c;
            run += __shfl_sync(0xFFFFFFFFu, s, 31);
        }
        if (lane == 0) so2p[na2] = run;
    }
    __syncthreads();

    // 8. reorder idx2 into slot order; publish offsets
    for (int s = tid; s < na2; s += nthr) {
        int jb = g_jperm[s];
        int src = so2[jb], dst = so2p[s], c = sc2[jb];
        for (int k = 0; k < c; k++) g_idx2p[dst + k] = g_idx2[src + k];
    }
    for (int t = tid; t <= na1; t += nthr) g_off1[t]  = so1[t];
    for (int t = tid; t <= na2; t += nthr) g_off2p[t] = so2p[t];
    __syncthreads();

    // 9. gather packed float4 data
    float l = ls[0];
    float invl2 = 1.0f / (l * l);
    for (int t = tid; t < n1; t += nthr) {
        int p = g_idx1[t];
        g_s1[t] = make_float4(d1[p], u1[3 * p] * invl2, u1[3 * p + 1] * invl2,
                              u1[3 * p + 2] * invl2);
    }
    for (int t = tid; t < n2; t += nthr) {
        int q = g_idx2p[t];
        g_s2p[t] = make_float4(d2[q], u2[3 * q], u2[3 * q + 1], u2[3 * q + 2]);
    }
}

// ------------------------------------------------------------------ main
// grid: (ceil(na2/256), na1), block 256. One thread per (ia, slot).
__global__ void __launch_bounds__(256) k_main(float* __restrict__ out,
                                              int na1, int na2,
                                              const float* __restrict__ ls) {
    extern __shared__ float4 smem[];
    float4* sp = smem;             // staged pairs of this ia   [PAIR_CAP]
    float4* sq = smem + PAIR_CAP;  // staged s2 range for block [<= n2]

    const int ia    = blockIdx.y;
    const int slot0 = blockIdx.x * blockDim.x;
    const int tid   = threadIdx.x;

    const int p0 = g_off1[ia], p1 = g_off1[ia + 1];
    const int np = p1 - p0;

    const int slot_end = min(slot0 + (int)blockDim.x, na2);
    const int qbase = g_off2p[slot0];
    const int qend  = g_off2p[slot_end];
    const int nq    = qend - qbase;

    for (int i = tid; i < np && i < PAIR_CAP; i += blockDim.x) sp[i] = g_s1[p0 + i];
    for (int i = tid; i < nq; i += blockDim.x) sq[i] = g_s2p[qbase + i];
    __syncthreads();

    const int slot = slot0 + tid;
    if (slot >= na2) return;

    const float l = ls[0];
    const float invl2 = 1.0f / (l * l);
    const float w = -0.5f * invl2;

    const int jb = g_jperm[slot];
    const int q0 = g_off2p[slot] - qbase;
    const int q1 = g_off2p[slot + 1] - qbase;

    float a00 = 0.f, a01 = 0.f, a02 = 0.f;
    float a10 = 0.f, a11 = 0.f, a12 = 0.f;
    float a20 = 0.f, a21 = 0.f, a22 = 0.f;

    for (int p = 0; p < np; p++) {
        const float4 P = (p < PAIR_CAP) ? sp[p] : g_s1[p0 + p];
        for (int q = q0; q < q1; q++) {
            const float4 Q = sq[q];
            float diff = P.x - Q.x;
            float d2v  = diff * diff;
            float k    = __expf(w * d2v);          // MUFU pipe
            float g    = fmaf(d2v, -invl2, 1.0f) * k;  // invl2 factor folded in P.yzw
            float b0 = g * Q.y, b1 = g * Q.z, b2 = g * Q.w;
            a00 = fmaf(P.y, b0, a00); a01 = fmaf(P.y, b1, a01); a02 = fmaf(P.y, b2, a02);
            a10 = fmaf(P.z, b0, a10); a11 = fmaf(P.z, b1, a11); a12 = fmaf(P.z, b2, a12);
            a20 = fmaf(P.w, b0, a20); a21 = fmaf(P.w, b1, a21); a22 = fmaf(P.w, b2, a22);
        }
    }

    const int ld = na2 * 3;
    float* o = out + (ia * 3) * ld + jb * 3;
    o[0] = a00; o[1] = a01; o[2] = a02; o += ld;
    o[0] = a10; o[1] = a11; o[2] = a12; o += ld;
    o[0] = a20; o[1] = a21; o[2] = a22;
}

// ------------------------------------------------------------------ launch
extern "C" void kernel_launch(void* const* d_in, const int* in_sizes, int n_in,
                              void* d_out, int out_size) {
    const float* d1 = (const float*)d_in[0];
    const float* u1 = (const float*)d_in[1];
    const float* d2 = (const float*)d_in[2];
    const float* u2 = (const float*)d_in[3];
    const float* ls = (const float*)d_in[4];
    const int*   i1 = (const int*)d_in[5];
    const int*   i2 = (const int*)d_in[6];
    float* out = (float*)d_out;

    int n1 = in_sizes[0];
    int n2 = in_sizes[2];
    int side = (int)(sqrt((double)out_size) + 0.5);
    int na1 = side / 3;
    int na2 = side / 3;

    k_prep<<<1, 1024>>>(d1, u1, d2, u2, ls, i1, i2, n1, n2, na1, na2);

    // dynamic smem: PAIR_CAP pairs + worst-case full s2 (n2 float4)
    int smem_bytes = (PAIR_CAP + n2) * (int)sizeof(float4);
    static int attr_done = 0;
    if (!attr_done) {
        cudaFuncSetAttribute(k_main, cudaFuncAttributeMaxDynamicSharedMemorySize,
                             smem_bytes > 48000 ? smem_bytes : 48000);
        attr_done = 1;
    }
    dim3 grid((na2 + 255) / 256, na1);
    k_main<<<grid, 256, smem_bytes>>>(out, na1, na2, ls);
}

// round 4
// speedup vs baseline: 1.5414x; 1.4757x over previous
#include <cuda_runtime.h>
#include <math.h>

// DSimilarity gradgrad, v4:
//  - single-block prep with register bitonic group sort + ballot-scan slot
//    permutation (kills the 45us serial prep of v3)
//  - s2 stored PADDED+TRANSPOSED per 32-slot warp-tile (sorted by group size):
//    k_main inner loads are perfectly coalesced LDG.128, zero divergence,
//    no bounds checks (padding rows have u2=0 -> contribute exactly 0)
//  - k_main: Q outer (registers), P inner (smem broadcast), ex2.approx for exp

#define MAXP   16384
#define MAXA   1024
#define MAXCNT 64
#define MAXW   64        // warp-tiles (na2/32)

__device__ float4 g_s1[MAXP];            // (d1, u1*invl2), atom-sorted
__device__ float4 g_s2t[MAXP * 32];      // padded transposed side-2 tiles
__device__ int    g_off1[MAXA + 1];
__device__ int    g_jperm[MAXA];         // slot -> jb
__device__ int    g_wbase[MAXW], g_wcmax[MAXW];
__device__ int    g_idx1[MAXP], g_idx2[MAXP];

// ---------------------------------------------------------- register group sort
__device__ __forceinline__ void sort_group(int* buf, int lo, int hi) {
    int c = hi - lo;
    if (c <= 1) return;
    if (c <= 32) {
        int v[32];
        #pragma unroll
        for (int i = 0; i < 32; i++) v[i] = (i < c) ? buf[lo + i] : 0x7FFFFFFF;
        #pragma unroll
        for (int k = 2; k <= 32; k <<= 1)
            #pragma unroll
            for (int j = k >> 1; j > 0; j >>= 1)
                #pragma unroll
                for (int i = 0; i < 32; i++) {
                    int l = i ^ j;
                    if (l > i) {
                        bool up = ((i & k) == 0);
                        int a = v[i], b = v[l];
                        if ((a > b) == up) { v[i] = b; v[l] = a; }
                    }
                }
        #pragma unroll
        for (int i = 0; i < 32; i++) if (i < c) buf[lo + i] = v[i];
    } else {
        for (int i = lo + 1; i < hi; i++) {
            int v = buf[i], j = i - 1;
            while (j >= lo && buf[j] > v) { buf[j + 1] = buf[j]; j--; }
            buf[j + 1] = v;
        }
    }
}

// ---------------------------------------------------------------- fused prep
__global__ void __launch_bounds__(1024) k_prep(
        const float* __restrict__ d1, const float* __restrict__ u1,
        const float* __restrict__ d2, const float* __restrict__ u2,
        const float* __restrict__ ls,
        const int* __restrict__ i1, const int* __restrict__ i2,
        int n1, int n2, int na1, int na2) {
    __shared__ int sc1[MAXA], sc2[MAXA];
    __shared__ int so1[MAXA + 1], so2[MAXA + 1];
    __shared__ int scur1[MAXA], scur2[MAXA];
    __shared__ int sbkt[MAXCNT], sbase[MAXCNT];
    __shared__ int swcmax[MAXW], swbase[MAXW];

    const int tid = threadIdx.x, nthr = blockDim.x;
    const int lane = tid & 31, warp = tid >> 5;
    const int NW = (na2 + 31) / 32;

    // 1. zero
    for (int t = tid; t < na1; t += nthr) sc1[t] = 0;
    for (int t = tid; t < na2; t += nthr) sc2[t] = 0;
    if (tid < MAXCNT) sbkt[tid] = 0;
    __syncthreads();

    // 2. histogram
    for (int t = tid; t < n1; t += nthr) atomicAdd(&sc1[i1[t]], 1);
    for (int t = tid; t < n2; t += nthr) atomicAdd(&sc2[i2[t]], 1);
    __syncthreads();

    // 3. exclusive scans (warp 0 side1, warp 1 side2)
    if (warp < 2) {
        int  na  = warp ? na2 : na1;
        int* cnt = warp ? sc2 : sc1;
        int* off = warp ? so2 : so1;
        int run = 0;
        for (int base = 0; base < na; base += 32) {
            int i = base + lane;
            int c = (i < na) ? cnt[i] : 0;
            int s = c;
            #pragma unroll
            for (int d = 1; d < 32; d <<= 1) {
                int t = __shfl_up_sync(0xFFFFFFFFu, s, d);
                if (lane >= d) s += t;
            }
            if (i < na) off[i] = run + s - c;
            run += __shfl_sync(0xFFFFFFFFu, s, 31);
        }
        if (lane == 0) off[na] = run;
    }
    __syncthreads();

    // 4. scatter (atomic order fixed up by the sort below)
    for (int t = tid; t < na1; t += nthr) scur1[t] = so1[t];
    for (int t = tid; t < na2; t += nthr) scur2[t] = so2[t];
    __syncthreads();
    for (int t = tid; t < n1; t += nthr) { int p = atomicAdd(&scur1[i1[t]], 1); g_idx1[p] = t; }
    for (int t = tid; t < n2; t += nthr) { int p = atomicAdd(&scur2[i2[t]], 1); g_idx2[p] = t; }
    __syncthreads();

    // 5. per-group register sort -> deterministic order
    for (int t = tid; t < na1 + na2; t += nthr) {
        if (t < na1) sort_group(g_idx1, so1[t], so1[t + 1]);
        else { int a = t - na1; sort_group(g_idx2, so2[a], so2[a + 1]); }
    }
    __syncthreads();

    // 6. slot permutation: stable counting sort of jb by group count (ballot scan)
    for (int t = tid; t < na2; t += nthr) atomicAdd(&sbkt[min(sc2[t], MAXCNT - 1)], 1);
    __syncthreads();
    if (tid == 0) {
        int run = 0;
        for (int c = 0; c < MAXCNT; c++) { sbase[c] = run; run += sbkt[c]; }
    }
    __syncthreads();
    for (int c = warp; c < MAXCNT; c += 32) {
        int run = sbase[c];
        for (int b = 0; b < na2; b += 32) {
            int jb = b + lane;
            bool m = (jb < na2) && (min(sc2[jb], MAXCNT - 1) == c);
            unsigned bal = __ballot_sync(0xFFFFFFFFu, m);
            if (m) g_jperm[run + __popc(bal & ((1u << lane) - 1))] = jb;
            run += __popc(bal);
        }
    }
    __syncthreads();

    // 7. per-warp-tile max count + bases
    if (tid < NW) {
        int cm = 0;
        for (int l = 0; l < 32; l++) {
            int s = tid * 32 + l;
            if (s < na2) cm = max(cm, sc2[g_jperm[s]]);
        }
        swcmax[tid] = cm;
    }
    __syncthreads();
    if (tid == 0) {
        int run = 0;
        for (int w = 0; w < NW; w++) { swbase[w] = run; run += swcmax[w] * 32; }
    }
    __syncthreads();
    if (tid < NW) { g_wbase[tid] = swbase[tid]; g_wcmax[tid] = swcmax[tid]; }

    // 8. fill padded transposed s2 tiles (gather fused in)
    for (int s = tid; s < NW * 32; s += nthr) {
        int w = s >> 5, ln = s & 31;
        int cm = swcmax[w], base = swbase[w];
        int c = 0, src = 0;
        if (s < na2) { int jb = g_jperm[s]; c = sc2[jb]; src = so2[jb]; }
        for (int k = 0; k < cm; k++) {
            float4 v = make_float4(1.0f, 0.0f, 0.0f, 0.0f);   // u2=0 -> contributes 0
            if (k < c) {
                int q = g_idx2[src + k];
                v = make_float4(d2[q], u2[3 * q], u2[3 * q + 1], u2[3 * q + 2]);
            }
            g_s2t[base + k * 32 + ln] = v;
        }
    }

    // 9. side-1 gather (invl2 folded into u1)
    float l = ls[0];
    float invl2 = 1.0f / (l * l);
    for (int t = tid; t < n1; t += nthr) {
        int p = g_idx1[t];
        g_s1[t] = make_float4(d1[p], u1[3 * p] * invl2, u1[3 * p + 1] * invl2,
                              u1[3 * p + 2] * invl2);
    }
    for (int t = tid; t <= na1; t += nthr) g_off1[t] = so1[t];
}

// ------------------------------------------------------------------ main
// grid: (ceil(NW/4), na1), block 128. warp <-> 32-slot tile, thread <-> slot.
__global__ void __launch_bounds__(128) k_main(float* __restrict__ out,
                                              int na1, int na2, int NW,
                                              const float* __restrict__ ls) {
    __shared__ float4 sp[64];

    const int warp = threadIdx.x >> 5, lane = threadIdx.x & 31;
    const int wt = blockIdx.x * 4 + warp;
    const int ia = blockIdx.y;

    const int p0 = g_off1[ia];
    const int np = g_off1[ia + 1] - p0;
    const int npc = min(np, 64);

    for (int i = threadIdx.x; i < npc; i += 128) sp[i] = g_s1[p0 + i];
    __syncthreads();

    if (wt >= NW) return;

    const float l = ls[0];
    const float invl2 = 1.0f / (l * l);
    const float wl2e  = -0.5f * invl2 * 1.4426950408889634f;

    const int cm    = g_wcmax[wt];
    const int qbase = g_wbase[wt] + lane;

    float a00 = 0.f, a01 = 0.f, a02 = 0.f;
    float a10 = 0.f, a11 = 0.f, a12 = 0.f;
    float a20 = 0.f, a21 = 0.f, a22 = 0.f;

    for (int k = 0; k < cm; k++) {
        const float4 Q = g_s2t[qbase + k * 32];     // coalesced, L1/L2 resident
        for (int p = 0; p < npc; p++) {
            const float4 P = sp[p];                 // smem broadcast
            float diff = P.x - Q.x;
            float d2v  = diff * diff;
            float xx   = d2v * wl2e;
            float e;
            asm("ex2.approx.ftz.f32 %0, %1;" : "=f"(e) : "f"(xx));
            float gv = fmaf(d2v, -invl2, 1.0f) * e;
            float t0 = gv * P.y, t1 = gv * P.z, t2 = gv * P.w;
            a00 = fmaf(t0, Q.y, a00); a01 = fmaf(t0, Q.z, a01); a02 = fmaf(t0, Q.w, a02);
            a10 = fmaf(t1, Q.y, a10); a11 = fmaf(t1, Q.z, a11); a12 = fmaf(t1, Q.w, a12);
            a20 = fmaf(t2, Q.y, a20); a21 = fmaf(t2, Q.z, a21); a22 = fmaf(t2, Q.w, a22);
        }
        for (int p = 64; p < np; p++) {             // (practically never taken)
            const float4 P = g_s1[p0 + p];
            float diff = P.x - Q.x;
            float d2v  = diff * diff;
            float xx   = d2v * wl2e;
            float e;
            asm("ex2.approx.ftz.f32 %0, %1;" : "=f"(e) : "f"(xx));
            float gv = fmaf(d2v, -invl2, 1.0f) * e;
            float t0 = gv * P.y, t1 = gv * P.z, t2 = gv * P.w;
            a00 = fmaf(t0, Q.y, a00); a01 = fmaf(t0, Q.z, a01); a02 = fmaf(t0, Q.w, a02);
            a10 = fmaf(t1, Q.y, a10); a11 = fmaf(t1, Q.z, a11); a12 = fmaf(t1, Q.w, a12);
            a20 = fmaf(t2, Q.y, a20); a21 = fmaf(t2, Q.z, a21); a22 = fmaf(t2, Q.w, a22);
        }
    }

    const int slot = wt * 32 + lane;
    if (slot >= na2) return;
    const int jb = g_jperm[slot];
    const int ld = na2 * 3;
    float* o = out + (ia * 3) * ld + jb * 3;
    o[0] = a00; o[1] = a01; o[2] = a02; o += ld;
    o[0] = a10; o[1] = a11; o[2] = a12; o += ld;
    o[0] = a20; o[1] = a21; o[2] = a22;
}

// ------------------------------------------------------------------ launch
extern "C" void kernel_launch(void* const* d_in, const int* in_sizes, int n_in,
                              void* d_out, int out_size) {
    const float* d1 = (const float*)d_in[0];
    const float* u1 = (const float*)d_in[1];
    const float* d2 = (const float*)d_in[2];
    const float* u2 = (const float*)d_in[3];
    const float* ls = (const float*)d_in[4];
    const int*   i1 = (const int*)d_in[5];
    const int*   i2 = (const int*)d_in[6];
    float* out = (float*)d_out;

    int n1 = in_sizes[0];
    int n2 = in_sizes[2];
    int side = (int)(sqrt((double)out_size) + 0.5);
    int na1 = side / 3;
    int na2 = side / 3;
    int NW  = (na2 + 31) / 32;

    k_prep<<<1, 1024>>>(d1, u1, d2, u2, ls, i1, i2, n1, n2, na1, na2);

    dim3 grid((NW + 3) / 4, na1);
    k_main<<<grid, 128>>>(out, na1, na2, NW, ls);
}

// round 5
// speedup vs baseline: 1.5499x; 1.0055x over previous
#include <cuda_runtime.h>
#include <math.h>

// DSimilarity gradgrad, v5:
//  A: single-block CONTROL-ONLY prep (hist, scans, slot perm, tile bases)
//  B: grid-wide warp-per-atom ballot-compaction scatter -> deterministic
//     t-ordered CSR (side 1) and padded transposed tiles (side 2). No atomics,
//     no sorts, fully parallel.
//  k_main: 2x2 unrolled (k,p), padded trip counts, ex2.approx, coalesced LDG.

#define MAXP   16384
#define MAXA   1024
#define MAXCNT 64
#define MAXW   64

__device__ float4 g_s1[MAXP];            // (d1, u1*invl2), atom-major, t-ordered
__device__ float4 g_s2t[MAXW * 64 * 32]; // padded transposed side-2 tiles
__device__ int    g_off1[MAXA + 1];
__device__ int    g_jperm[MAXA];         // slot -> jb
__device__ int    g_wbase[MAXW], g_wcmax[MAXW];

// ---------------------------------------------------------------- A: control
__global__ void __launch_bounds__(1024) k_ctl(
        const int* __restrict__ i1, const int* __restrict__ i2,
        int n1, int n2, int na1, int na2) {
    __shared__ int sc1[MAXA], sc2[MAXA];
    __shared__ int so1[MAXA + 1];
    __shared__ int sbkt[MAXCNT], sbase[MAXCNT];
    __shared__ int swcmax[MAXW];

    const int tid = threadIdx.x, nthr = blockDim.x;
    const int lane = tid & 31, warp = tid >> 5;
    const int NW = (na2 + 31) / 32;

    for (int t = tid; t < na1; t += nthr) sc1[t] = 0;
    for (int t = tid; t < na2; t += nthr) sc2[t] = 0;
    if (tid < MAXCNT) sbkt[tid] = 0;
    __syncthreads();

    for (int t = tid; t < n1; t += nthr) atomicAdd(&sc1[i1[t]], 1);
    for (int t = tid; t < n2; t += nthr) atomicAdd(&sc2[i2[t]], 1);
    __syncthreads();

    // exclusive scan of side-1 counts -> g_off1
    if (warp == 0) {
        int run = 0;
        for (int base = 0; base < na1; base += 32) {
            int i = base + lane;
            int c = (i < na1) ? sc1[i] : 0;
            int s = c;
            #pragma unroll
            for (int d = 1; d < 32; d <<= 1) {
                int t = __shfl_up_sync(0xFFFFFFFFu, s, d);
                if (lane >= d) s += t;
            }
            if (i < na1) so1[i] = run + s - c;
            run += __shfl_sync(0xFFFFFFFFu, s, 31);
        }
        if (lane == 0) so1[na1] = run;
    }
    __syncthreads();
    for (int t = tid; t <= na1; t += nthr) g_off1[t] = so1[t];

    // slot permutation: stable counting sort of jb by group count (ballot scan)
    for (int t = tid; t < na2; t += nthr) atomicAdd(&sbkt[min(sc2[t], MAXCNT - 1)], 1);
    __syncthreads();
    if (tid == 0) {
        int run = 0;
        for (int c = 0; c < MAXCNT; c++) { sbase[c] = run; run += sbkt[c]; }
    }
    __syncthreads();
    for (int c = warp; c < MAXCNT; c += 32) {
        int run = sbase[c];
        for (int b = 0; b < na2; b += 32) {
            int jb = b + lane;
            bool m = (jb < na2) && (min(sc2[jb], MAXCNT - 1) == c);
            unsigned bal = __ballot_sync(0xFFFFFFFFu, m);
            if (m) g_jperm[run + __popc(bal & ((1u << lane) - 1))] = jb;
            run += __popc(bal);
        }
    }
    __syncthreads();

    // per-tile max count (rounded even) + bases
    if (tid < NW) {
        int cm = 0;
        for (int l = 0; l < 32; l++) {
            int s = tid * 32 + l;
            if (s < na2) cm = max(cm, sc2[g_jperm[s]]);
        }
        swcmax[tid] = (cm + 1) & ~1;     // even for k-unroll-2
    }
    __syncthreads();
    if (tid == 0) {
        int run = 0;
        for (int w = 0; w < NW; w++) {
            g_wbase[w] = run;
            g_wcmax[w] = swcmax[w];
            run += swcmax[w] * 32;
        }
    }
}

// ------------------------------------------------------- B: grid-wide scatter
// one warp per atom (side 1) or per slot (side 2); ballot compaction gives
// deterministic t-ascending order without atomics or sorting.
__global__ void __launch_bounds__(256) k_fill(
        const float* __restrict__ d1, const float* __restrict__ u1,
        const float* __restrict__ d2, const float* __restrict__ u2,
        const float* __restrict__ ls,
        const int* __restrict__ i1, const int* __restrict__ i2,
        int n1, int n2, int na1, int na2) {
    const int lane = threadIdx.x & 31;
    const int w = blockIdx.x * (blockDim.x >> 5) + (threadIdx.x >> 5);

    if (w < na1) {
        // side 1: atom ia -> g_s1[off1[ia] ...] in t order, invl2 folded
        const int ia = w;
        const float l = ls[0];
        const float invl2 = 1.0f / (l * l);
        int run = g_off1[ia];
        for (int tb = 0; tb < n1; tb += 32) {
            int t = tb + lane;
            bool m = (t < n1) && (i1[t] == ia);
            unsigned bal = __ballot_sync(0xFFFFFFFFu, m);
            if (m) {
                int pos = run + __popc(bal & ((1u << lane) - 1));
                g_s1[pos] = make_float4(d1[t], u1[3 * t] * invl2,
                                        u1[3 * t + 1] * invl2, u1[3 * t + 2] * invl2);
            }
            run += __popc(bal);
        }
    } else if (w < na1 + na2) {
        // side 2: slot s -> column lane of its tile, padded to cm with zero-u
        const int s = w - na1;
        const int jb = g_jperm[s];
        const int wt = s >> 5, ln = s & 31;
        const int base = g_wbase[wt], cm = g_wcmax[wt];
        int run = 0;
        for (int tb = 0; tb < n2; tb += 32) {
            int t = tb + lane;
            bool m = (t < n2) && (i2[t] == jb);
            unsigned bal = __ballot_sync(0xFFFFFFFFu, m);
            if (m) {
                int k = run + __popc(bal & ((1u << lane) - 1));
                g_s2t[base + k * 32 + ln] =
                    make_float4(d2[t], u2[3 * t], u2[3 * t + 1], u2[3 * t + 2]);
            }
            run += __popc(bal);
        }
        for (int k = run + lane; k < cm; k += 32)
            g_s2t[base + k * 32 + ln] = make_float4(1.0f, 0.0f, 0.0f, 0.0f);
    }
}

// ------------------------------------------------------------------ main
#define BODY(P, Q)                                                             \
    {                                                                          \
        float diff = (P).x - (Q).x;                                            \
        float d2v  = diff * diff;                                              \
        float xx   = d2v * wl2e;                                               \
        float e;                                                               \
        asm("ex2.approx.ftz.f32 %0, %1;" : "=f"(e) : "f"(xx));                 \
        float gv = fmaf(d2v, -invl2, 1.0f) * e;                                \
        float t0 = gv * (P).y, t1 = gv * (P).z, t2 = gv * (P).w;               \
        a00 = fmaf(t0, (Q).y, a00); a01 = fmaf(t0, (Q).z, a01); a02 = fmaf(t0, (Q).w, a02); \
        a10 = fmaf(t1, (Q).y, a10); a11 = fmaf(t1, (Q).z, a11); a12 = fmaf(t1, (Q).w, a12); \
        a20 = fmaf(t2, (Q).y, a20); a21 = fmaf(t2, (Q).z, a21); a22 = fmaf(t2, (Q).w, a22); \
    }

__global__ void __launch_bounds__(128) k_main(float* __restrict__ out,
                                              int na1, int na2, int NW,
                                              const float* __restrict__ ls) {
    __shared__ float4 sp[66];

    const int warp = threadIdx.x >> 5, lane = threadIdx.x & 31;
    const int wt = blockIdx.x * 4 + warp;
    const int ia = blockIdx.y;

    const int p0 = g_off1[ia];
    const int np = g_off1[ia + 1] - p0;
    const int npc  = min(np, 64);
    const int npc2 = (npc + 1) & ~1;

    for (int i = threadIdx.x; i < npc; i += 128) sp[i] = g_s1[p0 + i];
    if (threadIdx.x == 0 && npc2 != npc)
        sp[npc] = make_float4(0.0f, 0.0f, 0.0f, 0.0f);   // zero-u pad: contributes 0
    __syncthreads();

    if (wt >= NW) return;

    const float l = ls[0];
    const float invl2 = 1.0f / (l * l);
    const float wl2e  = -0.5f * invl2 * 1.4426950408889634f;

    const int cm    = g_wcmax[wt];                  // even
    const int qbase = g_wbase[wt] + lane;

    float a00 = 0.f, a01 = 0.f, a02 = 0.f;
    float a10 = 0.f, a11 = 0.f, a12 = 0.f;
    float a20 = 0.f, a21 = 0.f, a22 = 0.f;

    for (int k = 0; k < cm; k += 2) {
        const float4 Qa = g_s2t[qbase + k * 32];         // coalesced LDG.128
        const float4 Qb = g_s2t[qbase + (k + 1) * 32];
        for (int p = 0; p < npc2; p += 2) {
            const float4 P0 = sp[p];
            const float4 P1 = sp[p + 1];
            BODY(P0, Qa); BODY(P0, Qb);
            BODY(P1, Qa); BODY(P1, Qb);
        }
        for (int p = 64; p < np; p++) {                  // practically never taken
            const float4 P = g_s1[p0 + p];
            BODY(P, Qa); BODY(P, Qb);
        }
    }

    const int slot = wt * 32 + lane;
    if (slot >= na2) return;
    const int jb = g_jperm[slot];
    const int ld = na2 * 3;
    float* o = out + (ia * 3) * ld + jb * 3;
    o[0] = a00; o[1] = a01; o[2] = a02; o += ld;
    o[0] = a10; o[1] = a11; o[2] = a12; o += ld;
    o[0] = a20; o[1] = a21; o[2] = a22;
}

// ------------------------------------------------------------------ launch
extern "C" void kernel_launch(void* const* d_in, const int* in_sizes, int n_in,
                              void* d_out, int out_size) {
    const float* d1 = (const float*)d_in[0];
    const float* u1 = (const float*)d_in[1];
    const float* d2 = (const float*)d_in[2];
    const float* u2 = (const float*)d_in[3];
    const float* ls = (const float*)d_in[4];
    const int*   i1 = (const int*)d_in[5];
    const int*   i2 = (const int*)d_in[6];
    float* out = (float*)d_out;

    int n1 = in_sizes[0];
    int n2 = in_sizes[2];
    int side = (int)(sqrt((double)out_size) + 0.5);
    int na1 = side / 3;
    int na2 = side / 3;
    int NW  = (na2 + 31) / 32;

    k_ctl<<<1, 1024>>>(i1, i2, n1, n2, na1, na2);

    int warps_needed = na1 + na2;
    int blocksB = (warps_needed * 32 + 255) / 256;
    k_fill<<<blocksB, 256>>>(d1, u1, d2, u2, ls, i1, i2, n1, n2, na1, na2);

    dim3 grid((NW + 3) / 4, na1);
    k_main<<<grid, 128>>>(out, na1, na2, NW, ls);
}

// round 6
// speedup vs baseline: 2.1747x; 1.4031x over previous
#include <cuda_runtime.h>
#include <math.h>

// DSimilarity gradgrad, v6 — low-rank Chebyshev reformulation.
// gg(x,y) ~= sum_{m,n<32} C[m][n] T_m(sx) T_n(sy)  (degree-31 tensor interpolant
// on the data box; gg is entire -> error << 1e-7 at l=1).
// out = F1 (1500x32) * C * F2^T (32x1500): one small GEMM instead of 16M pair
// evaluations.
// Stages: k_zero -> k_coeff (minmax + node grid + 2D DCT, 1 block)
//         -> k_feat (warp/pair, T_m = __cosf(m*acos(s)), atomicAdd scatter)
//         -> k_fold (H2 = F2 * C^T) -> k_gemm (64x64 tiles, 4x4/thread).

#define NC     32          // Chebyshev nodes == kept coefficients per dim
#define ROWCAP 2048        // max padded rows of F1/F2 (na*3 rounded to 64)

__device__ float g_F1[ROWCAP * NC];
__device__ float g_F2[ROWCAP * NC];
__device__ float g_H2[ROWCAP * NC];
__device__ float g_C[NC * NC];
__device__ float g_dom[2];          // center, half-width

// ------------------------------------------------------------------ zero
__global__ void k_zero() {
    int t = blockIdx.x * blockDim.x + threadIdx.x;
    if (t < ROWCAP * NC) { g_F1[t] = 0.0f; g_F2[t] = 0.0f; }
}

// ------------------------------------------------------------------ coeff
// One block, 1024 threads: minmax of all distances, then H[i][j]=gg(nodes),
// then separable 2D DCT -> C[32][32].
__global__ void __launch_bounds__(1024) k_coeff(
        const float* __restrict__ d1, const float* __restrict__ d2,
        const float* __restrict__ ls, int n1, int n2) {
    __shared__ float sH[NC][NC + 1];
    __shared__ float sD[NC][NC + 1];
    __shared__ float slo[32], shi[32];

    const int tid = threadIdx.x;
    const int lane = tid & 31, warp = tid >> 5;

    // minmax over d1 and d2
    float lo = 3.0e38f, hi = -3.0e38f;
    for (int t = tid; t < n1; t += 1024) { float v = d1[t]; lo = fminf(lo, v); hi = fmaxf(hi, v); }
    for (int t = tid; t < n2; t += 1024) { float v = d2[t]; lo = fminf(lo, v); hi = fmaxf(hi, v); }
    #pragma unroll
    for (int d = 16; d > 0; d >>= 1) {
        lo = fminf(lo, __shfl_xor_sync(0xFFFFFFFFu, lo, d));
        hi = fmaxf(hi, __shfl_xor_sync(0xFFFFFFFFu, hi, d));
    }
    if (lane == 0) { slo[warp] = lo; shi[warp] = hi; }
    __syncthreads();
    if (tid == 0) {
        float l2 = 3.0e38f, h2 = -3.0e38f;
        for (int w = 0; w < 32; w++) { l2 = fminf(l2, slo[w]); h2 = fmaxf(h2, shi[w]); }
        float center = 0.5f * (l2 + h2);
        float half   = fmaxf(0.5f * (h2 - l2), 1e-6f);
        g_dom[0] = center; g_dom[1] = half;
        slo[0] = center; shi[0] = half;
    }
    __syncthreads();
    const float center = slo[0], half = shi[0];
    const float lsv = ls[0];
    const float invl2 = 1.0f / (lsv * lsv);

    // node grid:  H[i][j] = gg(x_i, y_j),  x_i = center + half*cos(pi(i+.5)/NC)
    {
        int i = tid >> 5, j = tid & 31;
        float xi = center + half * cospif((i + 0.5f) / NC);
        float yj = center + half * cospif((j + 0.5f) / NC);
        float diff = xi - yj;
        float t2 = diff * diff * invl2;
        sH[i][j] = (invl2 - t2 * invl2) * invl2 == 0.0f  // (never true; keep fp order simple)
                   ? 0.0f
                   : (invl2 - t2 * invl2 * invl2 / invl2 * invl2) * 0.0f + // no-op guard removed below
                     (invl2 - t2 * invl2) * expf(-0.5f * t2);
        // NOTE: gg = (invl2 - diff^2*invl2^2)*exp(-0.5*diff^2*invl2)
        //          = (invl2 - t2*invl2)*exp(-0.5*t2)   with t2 = diff^2*invl2.
        sH[i][j] = (invl2 - t2 * invl2) * expf(-0.5f * t2);
    }
    __syncthreads();

    // D[m][j] = sum_i H[i][j] * cos(pi*m*(2i+1)/(2*NC))
    {
        int m = tid >> 5, j = tid & 31;
        float s = 0.0f;
        for (int i = 0; i < NC; i++)
            s += sH[i][j] * cospif(m * (2 * i + 1) / (2.0f * NC));
        sD[m][j] = s;
    }
    __syncthreads();

    // C[m][n] = (gm*gn/NC^2) sum_j D[m][j] * cos(pi*n*(2j+1)/(2*NC))
    {
        int m = tid >> 5, n = tid & 31;
        float s = 0.0f;
        for (int j = 0; j < NC; j++)
            s += sD[m][j] * cospif(n * (2 * j + 1) / (2.0f * NC));
        float gm = (m ? 2.0f : 1.0f) * (n ? 2.0f : 1.0f) / (float)(NC * NC);
        g_C[m * NC + n] = s * gm;
    }
}

// ------------------------------------------------------------------ features
// one warp per pair; lane = Chebyshev order m. T_m(s) = cos(m * acos(s)).
__global__ void __launch_bounds__(256) k_feat(
        const float* __restrict__ d1, const float* __restrict__ u1,
        const float* __restrict__ d2, const float* __restrict__ u2,
        const int* __restrict__ i1, const int* __restrict__ i2,
        int n1, int n2) {
    const int lane = threadIdx.x & 31;
    const int w = blockIdx.x * (blockDim.x >> 5) + (threadIdx.x >> 5);
    const float center = g_dom[0], half = g_dom[1];

    if (w < n1) {
        const int p = w;
        float s = (d1[p] - center) / half;
        s = fminf(1.0f, fmaxf(-1.0f, s));
        float th = acosf(s);
        float T = __cosf(lane * th);
        float ux = u1[3 * p], uy = u1[3 * p + 1], uz = u1[3 * p + 2];
        int base = i1[p] * (3 * NC) + lane;
        atomicAdd(&g_F1[base],           ux * T);
        atomicAdd(&g_F1[base + NC],      uy * T);
        atomicAdd(&g_F1[base + 2 * NC],  uz * T);
    } else if (w < n1 + n2) {
        const int q = w - n1;
        float s = (d2[q] - center) / half;
        s = fminf(1.0f, fmaxf(-1.0f, s));
        float th = acosf(s);
        float T = __cosf(lane * th);
        float ux = u2[3 * q], uy = u2[3 * q + 1], uz = u2[3 * q + 2];
        int base = i2[q] * (3 * NC) + lane;
        atomicAdd(&g_F2[base],           ux * T);
        atomicAdd(&g_F2[base + NC],      uy * T);
        atomicAdd(&g_F2[base + 2 * NC],  uz * T);
    }
}

// ------------------------------------------------------------------ fold
// H2[J][m] = sum_n C[m][n] * F2[J][n]
__global__ void __launch_bounds__(256) k_fold(int jrows) {
    int gid = blockIdx.x * blockDim.x + threadIdx.x;
    if (gid >= jrows * NC) return;
    int J = gid >> 5, m = gid & 31;
    const float* f2 = &g_F2[J * NC];
    const float* c  = &g_C[m * NC];
    float s = 0.0f;
    #pragma unroll
    for (int n = 0; n < NC; n++) s = fmaf(c[n], f2[n], s);
    g_H2[J * NC + m] = s;
}

// ------------------------------------------------------------------ GEMM
// out[I][J] = sum_m F1[I][m] * H2[J][m].  64x64 tile, 256 threads, 4x4/thread.
// Smem stored K-major ([k][row]) so fragments load as float4.
__global__ void __launch_bounds__(256) k_gemm(float* __restrict__ out,
                                              int nrows, int ncols) {
    __shared__ float As[NC][64];
    __shared__ float Bs[NC][64];

    const int tx = threadIdx.x & 15, ty = threadIdx.x >> 4;   // 16x16
    const int Ibase = blockIdx.y * 64;
    const int Jbase = blockIdx.x * 64;

    // load tiles: thread t loads 8 elements of each matrix (rows padded+zeroed)
    {
        int t = threadIdx.x;
        #pragma unroll
        for (int r = 0; r < 8; r++) {
            int e = t + r * 256;          // 0..2047
            int row = e >> 5, k = e & 31; // row 0..63, k 0..31
            As[k][row] = g_F1[(Ibase + row) * NC + k];
            Bs[k][row] = g_H2[(Jbase + row) * NC + k];
        }
    }
    __syncthreads();

    float acc[4][4] = {};
    #pragma unroll
    for (int k = 0; k < NC; k++) {
        float4 a = *(const float4*)&As[k][ty * 4];
        float4 b = *(const float4*)&Bs[k][tx * 4];
        float av[4] = {a.x, a.y, a.z, a.w};
        float bv[4] = {b.x, b.y, b.z, b.w};
        #pragma unroll
        for (int i = 0; i < 4; i++)
            #pragma unroll
            for (int j = 0; j < 4; j++)
                acc[i][j] = fmaf(av[i], bv[j], acc[i][j]);
    }

    #pragma unroll
    for (int i = 0; i < 4; i++) {
        int I = Ibase + ty * 4 + i;
        if (I >= nrows) break;
        #pragma unroll
        for (int j = 0; j < 4; j++) {
            int J = Jbase + tx * 4 + j;
            if (J < ncols) out[I * ncols + J] = acc[i][j];
        }
    }
}

// ------------------------------------------------------------------ launch
extern "C" void kernel_launch(void* const* d_in, const int* in_sizes, int n_in,
                              void* d_out, int out_size) {
    const float* d1 = (const float*)d_in[0];
    const float* u1 = (const float*)d_in[1];
    const float* d2 = (const float*)d_in[2];
    const float* u2 = (const float*)d_in[3];
    const float* ls = (const float*)d_in[4];
    const int*   i1 = (const int*)d_in[5];
    const int*   i2 = (const int*)d_in[6];
    float* out = (float*)d_out;

    int n1 = in_sizes[0];
    int n2 = in_sizes[2];
    int side = (int)(sqrt((double)out_size) + 0.5);
    int nrows = side;            // na1*3
    int ncols = side;            // na2*3

    k_zero<<<(ROWCAP * NC + 1023) / 1024, 1024>>>();
    k_coeff<<<1, 1024>>>(d1, d2, ls, n1, n2);

    int warps = n1 + n2;
    k_feat<<<(warps * 32 + 255) / 256, 256>>>(d1, u1, d2, u2, i1, i2, n1, n2);

    int jpad = ((ncols + 63) / 64) * 64;
    k_fold<<<(jpad * NC + 255) / 256, 256>>>(jpad);

    dim3 grid((ncols + 63) / 64, (nrows + 63) / 64);
    k_gemm<<<grid, 256>>>(out, nrows, ncols);
}

// round 7
// speedup vs baseline: 2.4980x; 1.1487x over previous
#include <cuda_runtime.h>
#include <math.h>

// DSimilarity gradgrad, v7 — Chebyshev low-rank, fold fused into GEMM.
// gg(x,y) ~= sum_{m,n<32} C[m][n] T_m(sx) T_n(sy); out = F1 * C * F2^T.
// Stages: k_zero -> k_coeff (minmax + node grid + 2D DCT, 1 block)
//         -> k_feat (warp/pair feature scatter, atomicAdd)
//         -> k_gemm (64x64 tiles; folds C into the B tile in-block).

#define NC     32
#define ROWCAP 2048

__device__ float g_F1[ROWCAP * NC];
__device__ float g_F2[ROWCAP * NC];
__device__ float g_C[NC * NC];
__device__ float g_dom[2];          // center, half-width

// ------------------------------------------------------------------ zero
__global__ void k_zero() {
    int t = blockIdx.x * blockDim.x + threadIdx.x;
    if (t < ROWCAP * NC) { g_F1[t] = 0.0f; g_F2[t] = 0.0f; }
}

// ------------------------------------------------------------------ coeff
__global__ void __launch_bounds__(1024) k_coeff(
        const float* __restrict__ d1, const float* __restrict__ d2,
        const float* __restrict__ ls, int n1, int n2) {
    __shared__ float sH[NC][NC + 1];
    __shared__ float sD[NC][NC + 1];
    __shared__ float slo[32], shi[32];

    const int tid = threadIdx.x;
    const int lane = tid & 31, warp = tid >> 5;

    // minmax over d1 and d2
    float lo = 3.0e38f, hi = -3.0e38f;
    for (int t = tid; t < n1; t += 1024) { float v = d1[t]; lo = fminf(lo, v); hi = fmaxf(hi, v); }
    for (int t = tid; t < n2; t += 1024) { float v = d2[t]; lo = fminf(lo, v); hi = fmaxf(hi, v); }
    #pragma unroll
    for (int d = 16; d > 0; d >>= 1) {
        lo = fminf(lo, __shfl_xor_sync(0xFFFFFFFFu, lo, d));
        hi = fmaxf(hi, __shfl_xor_sync(0xFFFFFFFFu, hi, d));
    }
    if (lane == 0) { slo[warp] = lo; shi[warp] = hi; }
    __syncthreads();
    if (tid == 0) {
        float l2 = 3.0e38f, h2 = -3.0e38f;
        for (int w = 0; w < 32; w++) { l2 = fminf(l2, slo[w]); h2 = fmaxf(h2, shi[w]); }
        float center = 0.5f * (l2 + h2);
        float half   = fmaxf(0.5f * (h2 - l2), 1e-6f);
        g_dom[0] = center; g_dom[1] = half;
        slo[0] = center; shi[0] = half;
    }
    __syncthreads();
    const float center = slo[0], half = shi[0];
    const float lsv = ls[0];
    const float invl2 = 1.0f / (lsv * lsv);

    // node grid: H[i][j] = gg(x_i, y_j)
    {
        int i = tid >> 5, j = tid & 31;
        float xi = center + half * cospif((i + 0.5f) / NC);
        float yj = center + half * cospif((j + 0.5f) / NC);
        float diff = xi - yj;
        float t2 = diff * diff * invl2;
        sH[i][j] = (invl2 - t2 * invl2) * expf(-0.5f * t2);
    }
    __syncthreads();

    // D[m][j] = sum_i H[i][j] * cos(pi*m*(2i+1)/(2*NC))
    {
        int m = tid >> 5, j = tid & 31;
        float s = 0.0f;
        for (int i = 0; i < NC; i++)
            s += sH[i][j] * cospif(m * (2 * i + 1) / (2.0f * NC));
        sD[m][j] = s;
    }
    __syncthreads();

    // C[m][n] = (gm/NC^2) sum_j D[m][j] * cos(pi*n*(2j+1)/(2*NC))
    {
        int m = tid >> 5, n = tid & 31;
        float s = 0.0f;
        for (int j = 0; j < NC; j++)
            s += sD[m][j] * cospif(n * (2 * j + 1) / (2.0f * NC));
        float gm = (m ? 2.0f : 1.0f) * (n ? 2.0f : 1.0f) / (float)(NC * NC);
        g_C[m * NC + n] = s * gm;
    }
}

// ------------------------------------------------------------------ features
// one warp per pair; lane = Chebyshev order m. T_m(s) = cos(m*acos(s)).
__global__ void __launch_bounds__(256) k_feat(
        const float* __restrict__ d1, const float* __restrict__ u1,
        const float* __restrict__ d2, const float* __restrict__ u2,
        const int* __restrict__ i1, const int* __restrict__ i2,
        int n1, int n2) {
    const int lane = threadIdx.x & 31;
    const int w = blockIdx.x * (blockDim.x >> 5) + (threadIdx.x >> 5);
    const float center = g_dom[0], half = g_dom[1];

    if (w < n1) {
        const int p = w;
        float s = (d1[p] - center) / half;
        s = fminf(1.0f, fmaxf(-1.0f, s));
        float th = acosf(s);
        float T = __cosf(lane * th);
        float ux = u1[3 * p], uy = u1[3 * p + 1], uz = u1[3 * p + 2];
        int base = i1[p] * (3 * NC) + lane;
        atomicAdd(&g_F1[base],           ux * T);
        atomicAdd(&g_F1[base + NC],      uy * T);
        atomicAdd(&g_F1[base + 2 * NC],  uz * T);
    } else if (w < n1 + n2) {
        const int q = w - n1;
        float s = (d2[q] - center) / half;
        s = fminf(1.0f, fmaxf(-1.0f, s));
        float th = acosf(s);
        float T = __cosf(lane * th);
        float ux = u2[3 * q], uy = u2[3 * q + 1], uz = u2[3 * q + 2];
        int base = i2[q] * (3 * NC) + lane;
        atomicAdd(&g_F2[base],           ux * T);
        atomicAdd(&g_F2[base + NC],      uy * T);
        atomicAdd(&g_F2[base + 2 * NC],  uz * T);
    }
}

// ------------------------------------------------------------------ GEMM + fold
// out[I][J] = sum_m F1[I][m] * (sum_n C[m][n] F2[J][n]).
// 64x64 tile, 256 threads, 4x4/thread; C folded into the B tile in smem.
__global__ void __launch_bounds__(256) k_gemm(float* __restrict__ out,
                                              int nrows, int ncols) {
    __shared__ float As[NC][64];
    __shared__ float Bs[NC][64];
    __shared__ float sF2[64][NC + 1];
    __shared__ float sC[NC][NC + 1];

    const int t  = threadIdx.x;
    const int tx = t & 15, ty = t >> 4;            // 16x16
    const int Ibase = blockIdx.y * 64;
    const int Jbase = blockIdx.x * 64;

    // load C (4KB) and tiles
    #pragma unroll
    for (int e = t; e < NC * NC; e += 256) sC[e >> 5][e & 31] = g_C[e];
    #pragma unroll
    for (int r = 0; r < 8; r++) {
        int e = t + r * 256;            // 0..2047
        int row = e >> 5, k = e & 31;   // row 0..63, k 0..31
        As[k][row]  = g_F1[(Ibase + row) * NC + k];
        sF2[row][k] = g_F2[(Jbase + row) * NC + k];
    }
    __syncthreads();

    // fold: Bs[k][row] = sum_n C[k][n] * F2[Jbase+row][n]
    // lanes: consecutive k (stride 33 in sC -> conflict-free), row broadcast.
    #pragma unroll
    for (int r = 0; r < 8; r++) {
        int e = t + r * 256;
        int row = e >> 5, k = e & 31;
        float s = 0.0f;
        #pragma unroll
        for (int n = 0; n < NC; n++) s = fmaf(sC[k][n], sF2[row][n], s);
        Bs[k][row] = s;
    }
    __syncthreads();

    float acc[4][4] = {};
    #pragma unroll
    for (int k = 0; k < NC; k++) {
        float4 a = *(const float4*)&As[k][ty * 4];
        float4 b = *(const float4*)&Bs[k][tx * 4];
        float av[4] = {a.x, a.y, a.z, a.w};
        float bv[4] = {b.x, b.y, b.z, b.w};
        #pragma unroll
        for (int i = 0; i < 4; i++)
            #pragma unroll
            for (int j = 0; j < 4; j++)
                acc[i][j] = fmaf(av[i], bv[j], acc[i][j]);
    }

    #pragma unroll
    for (int i = 0; i < 4; i++) {
        int I = Ibase + ty * 4 + i;
        if (I >= nrows) break;
        #pragma unroll
        for (int j = 0; j < 4; j++) {
            int J = Jbase + tx * 4 + j;
            if (J < ncols) out[I * ncols + J] = acc[i][j];
        }
    }
}

// ------------------------------------------------------------------ launch
extern "C" void kernel_launch(void* const* d_in, const int* in_sizes, int n_in,
                              void* d_out, int out_size) {
    const float* d1 = (const float*)d_in[0];
    const float* u1 = (const float*)d_in[1];
    const float* d2 = (const float*)d_in[2];
    const float* u2 = (const float*)d_in[3];
    const float* ls = (const float*)d_in[4];
    const int*   i1 = (const int*)d_in[5];
    const int*   i2 = (const int*)d_in[6];
    float* out = (float*)d_out;

    int n1 = in_sizes[0];
    int n2 = in_sizes[2];
    int side = (int)(sqrt((double)out_size) + 0.5);
    int nrows = side;            // na1*3
    int ncols = side;            // na2*3

    k_zero<<<(ROWCAP * NC + 1023) / 1024, 1024>>>();
    k_coeff<<<1, 1024>>>(d1, d2, ls, n1, n2);

    int warps = n1 + n2;
    k_feat<<<(warps * 32 + 255) / 256, 256>>>(d1, u1, d2, u2, i1, i2, n1, n2);

    dim3 grid((ncols + 63) / 64, (nrows + 63) / 64);
    k_gemm<<<grid, 256>>>(out, nrows, ncols);
}

// round 10
// speedup vs baseline: 3.5632x; 1.4264x over previous
#include <cuda_runtime.h>
#include <math.h>

// DSimilarity gradgrad, v8.1 — Chebyshev low-rank; 128x128x32 register-blocked GEMM.
// gg(x,y) ~= sum_{m,n<32} C[m][n] T_m(sx) T_n(sy); out = F1 * C * F2^T.
// Stages: k_zero (float4) -> k_coeff (1 block) -> k_feat (warp/pair scatter)
//         -> k_gemm (128x128 tile, 8x8/thread, C-fold fused in-block).

#define NC     32
#define ROWCAP 2048
#define TS     128          // block tile
#define LDT    132          // padded smem stride (16B-aligned float4 fragments)

__device__ float g_F1[ROWCAP * NC];
__device__ float g_F2[ROWCAP * NC];
__device__ float g_C[NC * NC];
__device__ float g_dom[2];          // center, half-width

// ------------------------------------------------------------------ zero
__global__ void k_zero() {
    int t = blockIdx.x * blockDim.x + threadIdx.x;
    float4 z = make_float4(0.f, 0.f, 0.f, 0.f);
    if (t < (ROWCAP * NC) / 4) {
        ((float4*)g_F1)[t] = z;
        ((float4*)g_F2)[t] = z;
    }
}

// ------------------------------------------------------------------ coeff
__global__ void __launch_bounds__(1024) k_coeff(
        const float* __restrict__ d1, const float* __restrict__ d2,
        const float* __restrict__ ls, int n1, int n2) {
    __shared__ float sH[NC][NC + 1];
    __shared__ float sD[NC][NC + 1];
    __shared__ float slo[32], shi[32];

    const int tid = threadIdx.x;
    const int lane = tid & 31, warp = tid >> 5;

    float lo = 3.0e38f, hi = -3.0e38f;
    for (int t = tid; t < n1; t += 1024) { float v = d1[t]; lo = fminf(lo, v); hi = fmaxf(hi, v); }
    for (int t = tid; t < n2; t += 1024) { float v = d2[t]; lo = fminf(lo, v); hi = fmaxf(hi, v); }
    #pragma unroll
    for (int d = 16; d > 0; d >>= 1) {
        lo = fminf(lo, __shfl_xor_sync(0xFFFFFFFFu, lo, d));
        hi = fmaxf(hi, __shfl_xor_sync(0xFFFFFFFFu, hi, d));
    }
    if (lane == 0) { slo[warp] = lo; shi[warp] = hi; }
    __syncthreads();
    if (tid == 0) {
        float l2 = 3.0e38f, h2 = -3.0e38f;
        for (int w = 0; w < 32; w++) { l2 = fminf(l2, slo[w]); h2 = fmaxf(h2, shi[w]); }
        float center = 0.5f * (l2 + h2);
        float half   = fmaxf(0.5f * (h2 - l2), 1e-6f);
        g_dom[0] = center; g_dom[1] = half;
        slo[0] = center; shi[0] = half;
    }
    __syncthreads();
    const float center = slo[0], half = shi[0];
    const float lsv = ls[0];
    const float invl2 = 1.0f / (lsv * lsv);

    {
        int i = tid >> 5, j = tid & 31;
        float xi = center + half * cospif((i + 0.5f) / NC);
        float yj = center + half * cospif((j + 0.5f) / NC);
        float diff = xi - yj;
        float t2 = diff * diff * invl2;
        sH[i][j] = (invl2 - t2 * invl2) * expf(-0.5f * t2);
    }
    __syncthreads();
    {
        int m = tid >> 5, j = tid & 31;
        float s = 0.0f;
        for (int i = 0; i < NC; i++)
            s += sH[i][j] * cospif(m * (2 * i + 1) / (2.0f * NC));
        sD[m][j] = s;
    }
    __syncthreads();
    {
        int m = tid >> 5, n = tid & 31;
        float s = 0.0f;
        for (int j = 0; j < NC; j++)
            s += sD[m][j] * cospif(n * (2 * j + 1) / (2.0f * NC));
        float gm = (m ? 2.0f : 1.0f) * (n ? 2.0f : 1.0f) / (float)(NC * NC);
        g_C[m * NC + n] = s * gm;
    }
}

// ------------------------------------------------------------------ features
__global__ void __launch_bounds__(256) k_feat(
        const float* __restrict__ d1, const float* __restrict__ u1,
        const float* __restrict__ d2, const float* __restrict__ u2,
        const int* __restrict__ i1, const int* __restrict__ i2,
        int n1, int n2) {
    const int lane = threadIdx.x & 31;
    const int w = blockIdx.x * (blockDim.x >> 5) + (threadIdx.x >> 5);
    const float center = g_dom[0], half = g_dom[1];

    if (w < n1) {
        const int p = w;
        float s = (d1[p] - center) / half;
        s = fminf(1.0f, fmaxf(-1.0f, s));
        float th = acosf(s);
        float T = __cosf(lane * th);
        float ux = u1[3 * p], uy = u1[3 * p + 1], uz = u1[3 * p + 2];
        int base = i1[p] * (3 * NC) + lane;
        atomicAdd(&g_F1[base],           ux * T);
        atomicAdd(&g_F1[base + NC],      uy * T);
        atomicAdd(&g_F1[base + 2 * NC],  uz * T);
    } else if (w < n1 + n2) {
        const int q = w - n1;
        float s = (d2[q] - center) / half;
        s = fminf(1.0f, fmaxf(-1.0f, s));
        float th = acosf(s);
        float T = __cosf(lane * th);
        float ux = u2[3 * q], uy = u2[3 * q + 1], uz = u2[3 * q + 2];
        int base = i2[q] * (3 * NC) + lane;
        atomicAdd(&g_F2[base],           ux * T);
        atomicAdd(&g_F2[base + NC],      uy * T);
        atomicAdd(&g_F2[base + 2 * NC],  uz * T);
    }
}

// ------------------------------------------------------------------ GEMM + fold
// out[I][J] = sum_k F1[I][k] * (sum_n C[k][n] F2[J][n]).
// 128x128 tile, 256 threads (16x16), 8x8 per thread, K=32 resident in smem.
__global__ void __launch_bounds__(256) k_gemm(float* __restrict__ out,
                                              int nrows, int ncols) {
    __shared__ float As[NC * LDT];       // [k][row], padded
    __shared__ float Bs[NC * LDT];       // fold temp [row][32] then [k][row]
    __shared__ float sC[NC][NC + 1];

    const int t  = threadIdx.x;
    const int tx = t & 15, ty = t >> 4;          // 16x16 threads
    const int Ibase = blockIdx.y * TS;
    const int Jbase = blockIdx.x * TS;

    // --- stage A tile (k-major) + F2 tile (row-major temp in Bs) + C ---
    {
        const int row0 = t >> 5, k = t & 31;     // coalesced LDG pattern
        #pragma unroll
        for (int r = 0; r < 16; r++) {
            int row = row0 + r * 8;
            As[k * LDT + row] = g_F1[(Ibase + row) * NC + k];
            Bs[row * NC + k]  = g_F2[(Jbase + row) * NC + k];   // temp, row-major
        }
        #pragma unroll
        for (int e = t; e < NC * NC; e += 256) sC[e >> 5][e & 31] = g_C[e];
    }
    __syncthreads();

    // --- fold: Hrow[k] = sum_n C[k][n] * F2[row][n]; write k-major into Bs ---
    float hold[16];
    {
        const int k = t & 31, row0 = t >> 5;
        float cr[NC];
        #pragma unroll
        for (int n = 0; n < NC; n++) cr[n] = sC[k][n];   // conflict-free (stride 33)
        #pragma unroll
        for (int r = 0; r < 16; r++) {
            int row = row0 + r * 8;
            const float* f2 = &Bs[row * NC];             // broadcast within warp
            float s = 0.0f;
            #pragma unroll
            for (int n4 = 0; n4 < NC; n4 += 4) {
                float4 v = *(const float4*)&f2[n4];
                s = fmaf(cr[n4],     v.x, s);
                s = fmaf(cr[n4 + 1], v.y, s);
                s = fmaf(cr[n4 + 2], v.z, s);
                s = fmaf(cr[n4 + 3], v.w, s);
            }
            hold[r] = s;
        }
    }
    __syncthreads();                                     // all temp reads done
    {
        const int k = t & 31, row0 = t >> 5;
        #pragma unroll
        for (int r = 0; r < 16; r++)
            Bs[k * LDT + row0 + r * 8] = hold[r];
    }
    __syncthreads();

    // --- main: 8x8 register tile over K=32 ---
    float acc[8][8] = {};
    #pragma unroll
    for (int k = 0; k < NC; k++) {
        float4 a0 = *(const float4*)&As[k * LDT + ty * 8];
        float4 a1 = *(const float4*)&As[k * LDT + ty * 8 + 4];
        float4 b0 = *(const float4*)&Bs[k * LDT + tx * 8];
        float4 b1 = *(const float4*)&Bs[k * LDT + tx * 8 + 4];
        float av[8] = {a0.x, a0.y, a0.z, a0.w, a1.x, a1.y, a1.z, a1.w};
        float bv[8] = {b0.x, b0.y, b0.z, b0.w, b1.x, b1.y, b1.z, b1.w};
        #pragma unroll
        for (int i = 0; i < 8; i++)
            #pragma unroll
            for (int j = 0; j < 8; j++)
                acc[i][j] = fmaf(av[i], bv[j], acc[i][j]);
    }

    // --- write out (guarded float4 where possible) ---
    #pragma unroll
    for (int i = 0; i < 8; i++) {
        int I = Ibase + ty * 8 + i;
        if (I >= nrows) break;
        float* orow = out + (size_t)I * ncols;
        #pragma unroll
        for (int j4 = 0; j4 < 8; j4 += 4) {
            int J = Jbase + tx * 8 + j4;
            if (J + 3 < ncols) {
                float4 v = make_float4(acc[i][j4], acc[i][j4 + 1],
                                       acc[i][j4 + 2], acc[i][j4 + 3]);
                *(float4*)&orow[J] = v;
            } else {
                #pragma unroll
                for (int j = 0; j < 4; j++)
                    if (J + j < ncols) orow[J + j] = acc[i][j4 + j];
            }
        }
    }
}

// ------------------------------------------------------------------ launch
extern "C" void kernel_launch(void* const* d_in, const int* in_sizes, int n_in,
                              void* d_out, int out_size) {
    const float* d1 = (const float*)d_in[0];
    const float* u1 = (const float*)d_in[1];
    const float* d2 = (const float*)d_in[2];
    const float* u2 = (const float*)d_in[3];
    const float* ls = (const float*)d_in[4];
    const int*   i1 = (const int*)d_in[5];
    const int*   i2 = (const int*)d_in[6];
    float* out = (float*)d_out;

    int n1 = in_sizes[0];
    int n2 = in_sizes[2];
    int side = (int)(sqrt((double)out_size) + 0.5);
    int nrows = side;
    int ncols = side;

    k_zero<<<((ROWCAP * NC) / 4 + 255) / 256, 256>>>();
    k_coeff<<<1, 1024>>>(d1, d2, ls, n1, n2);

    int warps = n1 + n2;
    k_feat<<<(warps * 32 + 255) / 256, 256>>>(d1, u1, d2, u2, i1, i2, n1, n2);

    dim3 grid((ncols + TS - 1) / TS, (nrows + TS - 1) / TS);
    k_gemm<<<grid, 256>>>(out, nrows, ncols);
}

// round 11
// speedup vs baseline: 3.6959x; 1.0373x over previous
#include <cuda_runtime.h>
#include <math.h>

// DSimilarity gradgrad, v9 — Chebyshev low-rank, 3-kernel pipeline.
// gg(x,y) ~= sum_{m,n<32} C[m][n] T_m(sx) T_n(sy);  out = F1 * C * F2^T.
//  k_zero : zero F1/F2 + int-atomic minmax of all distances -> domain
//  k_feat : warp/pair feature scatter (atomicAdd)
//  k_gemm : 128x128x32 tile, 512 thr, 4x8/thread; C recomputed in-block
//           (node grid + 2D DCT, deterministic) and folded into B tile.

#define NC     32
#define ROWCAP 2048
#define TS     128
#define LDT    132          // padded smem stride (16B-aligned float4 fragments)

__device__ float g_F1[ROWCAP * NC];
__device__ float g_F2[ROWCAP * NC];
// int-encoded positive-float min/max; idempotent across graph replays
__device__ int g_dmin_bits = 0x7F7FFFFF;   // +FLT_MAX
__device__ int g_dmax_bits = 0;            // +0.0f

// ------------------------------------------------------------------ zero+minmax
__global__ void k_zero(const float* __restrict__ d1, const float* __restrict__ d2,
                       int n1, int n2) {
    int t = blockIdx.x * blockDim.x + threadIdx.x;
    int nthr = gridDim.x * blockDim.x;
    float4 z = make_float4(0.f, 0.f, 0.f, 0.f);
    if (t < (ROWCAP * NC) / 4) {
        ((float4*)g_F1)[t] = z;
        ((float4*)g_F2)[t] = z;
    }
    // minmax reduce (warp-local first, then one atomic per warp)
    float lo = 3.0e38f, hi = -3.0e38f;
    for (int i = t; i < n1; i += nthr) { float v = d1[i]; lo = fminf(lo, v); hi = fmaxf(hi, v); }
    for (int i = t; i < n2; i += nthr) { float v = d2[i]; lo = fminf(lo, v); hi = fmaxf(hi, v); }
    #pragma unroll
    for (int d = 16; d > 0; d >>= 1) {
        lo = fminf(lo, __shfl_xor_sync(0xFFFFFFFFu, lo, d));
        hi = fmaxf(hi, __shfl_xor_sync(0xFFFFFFFFu, hi, d));
    }
    if ((threadIdx.x & 31) == 0) {
        if (lo < 3.0e38f) atomicMin(&g_dmin_bits, __float_as_int(lo));
        if (hi > -3.0e38f) atomicMax(&g_dmax_bits, __float_as_int(hi));
    }
}

// ------------------------------------------------------------------ features
__global__ void __launch_bounds__(256) k_feat(
        const float* __restrict__ d1, const float* __restrict__ u1,
        const float* __restrict__ d2, const float* __restrict__ u2,
        const int* __restrict__ i1, const int* __restrict__ i2,
        int n1, int n2) {
    const int lane = threadIdx.x & 31;
    const int w = blockIdx.x * (blockDim.x >> 5) + (threadIdx.x >> 5);
    const float lo = __int_as_float(g_dmin_bits);
    const float hi = __int_as_float(g_dmax_bits);
    const float center = 0.5f * (lo + hi);
    const float half   = fmaxf(0.5f * (hi - lo), 1e-6f);

    if (w < n1) {
        const int p = w;
        float s = (d1[p] - center) / half;
        s = fminf(1.0f, fmaxf(-1.0f, s));
        float th = acosf(s);
        float T = __cosf(lane * th);
        float ux = u1[3 * p], uy = u1[3 * p + 1], uz = u1[3 * p + 2];
        int base = i1[p] * (3 * NC) + lane;
        atomicAdd(&g_F1[base],           ux * T);
        atomicAdd(&g_F1[base + NC],      uy * T);
        atomicAdd(&g_F1[base + 2 * NC],  uz * T);
    } else if (w < n1 + n2) {
        const int q = w - n1;
        float s = (d2[q] - center) / half;
        s = fminf(1.0f, fmaxf(-1.0f, s));
        float th = acosf(s);
        float T = __cosf(lane * th);
        float ux = u2[3 * q], uy = u2[3 * q + 1], uz = u2[3 * q + 2];
        int base = i2[q] * (3 * NC) + lane;
        atomicAdd(&g_F2[base],           ux * T);
        atomicAdd(&g_F2[base + NC],      uy * T);
        atomicAdd(&g_F2[base + 2 * NC],  uz * T);
    }
}

// ------------------------------------------------------------------ GEMM (+C +fold)
// out[I][J] = sum_k F1[I][k] * (sum_n C[k][n] F2[J][n]).
// 512 threads (16x32), 4x8 microtile. C computed in-block (identical in every
// block: node grid of gg + separable DCT), then folded into the B tile.
__global__ void __launch_bounds__(512) k_gemm(float* __restrict__ out,
                                              int nrows, int ncols,
                                              const float* __restrict__ ls) {
    __shared__ float As[NC * LDT];
    __shared__ float Bs[NC * LDT];       // fold temp [row][32] then [k][row]
    __shared__ float sH[NC][NC + 1];
    __shared__ float sD[NC][NC + 1];
    __shared__ float sC[NC][NC + 1];

    const int t  = threadIdx.x;
    const int Ibase = blockIdx.y * TS;
    const int Jbase = blockIdx.x * TS;

    const float lov = __int_as_float(g_dmin_bits);
    const float hiv = __int_as_float(g_dmax_bits);
    const float center = 0.5f * (lov + hiv);
    const float half   = fmaxf(0.5f * (hiv - lov), 1e-6f);
    const float lsv = ls[0];
    const float invl2 = 1.0f / (lsv * lsv);

    // --- C: node grid + 2D DCT (deterministic, identical across blocks) ---
    #pragma unroll
    for (int e = t; e < NC * NC; e += 512) {
        int i = e >> 5, j = e & 31;
        float xi = center + half * cospif((i + 0.5f) / NC);
        float yj = center + half * cospif((j + 0.5f) / NC);
        float diff = xi - yj;
        float t2 = diff * diff * invl2;
        sH[i][j] = (invl2 - t2 * invl2) * expf(-0.5f * t2);
    }
    __syncthreads();
    #pragma unroll
    for (int e = t; e < NC * NC; e += 512) {
        int m = e >> 5, j = e & 31;
        float s = 0.0f;
        #pragma unroll
        for (int i = 0; i < NC; i++)
            s += sH[i][j] * cospif(m * (2 * i + 1) / (2.0f * NC));
        sD[m][j] = s;
    }
    __syncthreads();
    #pragma unroll
    for (int e = t; e < NC * NC; e += 512) {
        int m = e >> 5, n = e & 31;
        float s = 0.0f;
        #pragma unroll
        for (int j = 0; j < NC; j++)
            s += sD[m][j] * cospif(n * (2 * j + 1) / (2.0f * NC));
        float gm = (m ? 2.0f : 1.0f) * (n ? 2.0f : 1.0f) / (float)(NC * NC);
        sC[m][n] = s * gm;
    }
    __syncthreads();

    // --- stage A (k-major) + F2 (row-major temp in Bs) ---
    {
        const int row0 = t >> 5, k = t & 31;     // row0 0..15, coalesced LDG
        #pragma unroll
        for (int r = 0; r < 8; r++) {
            int row = row0 + r * 16;
            As[k * LDT + row] = g_F1[(Ibase + row) * NC + k];
            Bs[row * NC + k]  = g_F2[(Jbase + row) * NC + k];
        }
    }
    __syncthreads();

    // --- fold: Bs[k][row] = sum_n C[k][n] * F2[row][n] ---
    float hold[8];
    {
        const int k = t & 31, row0 = t >> 5;
        float cr[NC];
        #pragma unroll
        for (int n = 0; n < NC; n++) cr[n] = sC[k][n];   // stride-33, conflict-free
        #pragma unroll
        for (int r = 0; r < 8; r++) {
            int row = row0 + r * 16;
            const float* f2 = &Bs[row * NC];
            float s = 0.0f;
            #pragma unroll
            for (int n4 = 0; n4 < NC; n4 += 4) {
                float4 v = *(const float4*)&f2[n4];
                s = fmaf(cr[n4],     v.x, s);
                s = fmaf(cr[n4 + 1], v.y, s);
                s = fmaf(cr[n4 + 2], v.z, s);
                s = fmaf(cr[n4 + 3], v.w, s);
            }
            hold[r] = s;
        }
    }
    __syncthreads();
    {
        const int k = t & 31, row0 = t >> 5;
        #pragma unroll
        for (int r = 0; r < 8; r++)
            Bs[k * LDT + row0 + r * 16] = hold[r];
    }
    __syncthreads();

    // --- main: 4x8 register tile over K=32 ---
    const int tx = t & 15, ty = t >> 4;          // tx: 8 cols, ty: 4 rows (32 groups)
    float acc[4][8] = {};
    #pragma unroll
    for (int k = 0; k < NC; k++) {
        float4 a  = *(const float4*)&As[k * LDT + ty * 4];
        float4 b0 = *(const float4*)&Bs[k * LDT + tx * 8];
        float4 b1 = *(const float4*)&Bs[k * LDT + tx * 8 + 4];
        float av[4] = {a.x, a.y, a.z, a.w};
        float bv[8] = {b0.x, b0.y, b0.z, b0.w, b1.x, b1.y, b1.z, b1.w};
        #pragma unroll
        for (int i = 0; i < 4; i++)
            #pragma unroll
            for (int j = 0; j < 8; j++)
                acc[i][j] = fmaf(av[i], bv[j], acc[i][j]);
    }

    // --- write out ---
    #pragma unroll
    for (int i = 0; i < 4; i++) {
        int I = Ibase + ty * 4 + i;
        if (I >= nrows) break;
        float* orow = out + (size_t)I * ncols;
        #pragma unroll
        for (int j4 = 0; j4 < 8; j4 += 4) {
            int J = Jbase + tx * 8 + j4;
            if (J + 3 < ncols) {
                float4 v = make_float4(acc[i][j4], acc[i][j4 + 1],
                                       acc[i][j4 + 2], acc[i][j4 + 3]);
                *(float4*)&orow[J] = v;
            } else {
                #pragma unroll
                for (int j = 0; j < 4; j++)
                    if (J + j < ncols) orow[J + j] = acc[i][j4 + j];
            }
        }
    }
}

// ------------------------------------------------------------------ launch
extern "C" void kernel_launch(void* const* d_in, const int* in_sizes, int n_in,
                              void* d_out, int out_size) {
    const float* d1 = (const float*)d_in[0];
    const float* u1 = (const float*)d_in[1];
    const float* d2 = (const float*)d_in[2];
    const float* u2 = (const float*)d_in[3];
    const float* ls = (const float*)d_in[4];
    const int*   i1 = (const int*)d_in[5];
    const int*   i2 = (const int*)d_in[6];
    float* out = (float*)d_out;

    int n1 = in_sizes[0];
    int n2 = in_sizes[2];
    int side = (int)(sqrt((double)out_size) + 0.5);
    int nrows = side;
    int ncols = side;

    k_zero<<<((ROWCAP * NC) / 4 + 255) / 256, 256>>>(d1, d2, n1, n2);

    int warps = n1 + n2;
    k_feat<<<(warps * 32 + 255) / 256, 256>>>(d1, u1, d2, u2, i1, i2, n1, n2);

    dim3 grid((ncols + TS - 1) / TS, (nrows + TS - 1) / TS);
    k_gemm<<<grid, 512>>>(out, nrows, ncols, ls);
}

// round 12
// speedup vs baseline: 4.8047x; 1.3000x over previous
#include <cuda_runtime.h>
#include <math.h>

// DSimilarity gradgrad, v10 — Chebyshev low-rank, 3-kernel pipeline.
//  k_zero : zero used F region + int-atomic minmax of distances -> domain
//  k_feat : block 0 computes C (table-driven DCT, ~0.3us, hidden);
//           blocks 1.. scatter features (warp/pair, atomicAdd)
//  k_gemm : 128x64x32 tile, 256 thr, 4x8/thread, C-fold fused; grid ~2/SM.

#define NC     32
#define ROWCAP 2048
#define TSI    128          // tile rows (I)
#define TSJ    64           // tile cols (J)
#define LDA    132          // padded smem strides (16B-aligned)
#define LDB    68

__device__ float g_F1[ROWCAP * NC];
__device__ float g_F2[ROWCAP * NC];
__device__ float g_C[NC * NC];
// int-encoded positive-float min/max; idempotent across graph replays
__device__ int g_dmin_bits = 0x7F7FFFFF;   // +FLT_MAX
__device__ int g_dmax_bits = 0;            // +0.0f

// ------------------------------------------------------------------ zero+minmax
__global__ void k_zero(const float* __restrict__ d1, const float* __restrict__ d2,
                       int n1, int n2, int nquads) {
    int t = blockIdx.x * blockDim.x + threadIdx.x;
    int nthr = gridDim.x * blockDim.x;
    float4 z = make_float4(0.f, 0.f, 0.f, 0.f);
    if (t < nquads) {
        ((float4*)g_F1)[t] = z;
        ((float4*)g_F2)[t] = z;
    }
    float lo = 3.0e38f, hi = -3.0e38f;
    for (int i = t; i < n1; i += nthr) { float v = d1[i]; lo = fminf(lo, v); hi = fmaxf(hi, v); }
    for (int i = t; i < n2; i += nthr) { float v = d2[i]; lo = fminf(lo, v); hi = fmaxf(hi, v); }
    #pragma unroll
    for (int d = 16; d > 0; d >>= 1) {
        lo = fminf(lo, __shfl_xor_sync(0xFFFFFFFFu, lo, d));
        hi = fmaxf(hi, __shfl_xor_sync(0xFFFFFFFFu, hi, d));
    }
    if ((threadIdx.x & 31) == 0) {
        if (lo < 3.0e38f) atomicMin(&g_dmin_bits, __float_as_int(lo));
        if (hi > -3.0e38f) atomicMax(&g_dmax_bits, __float_as_int(hi));
    }
}

// ------------------------------------------------------------------ features (+C in block 0)
__global__ void __launch_bounds__(256) k_feat(
        const float* __restrict__ d1, const float* __restrict__ u1,
        const float* __restrict__ d2, const float* __restrict__ u2,
        const float* __restrict__ ls,
        const int* __restrict__ i1, const int* __restrict__ i2,
        int n1, int n2) {
    const float lov = __int_as_float(g_dmin_bits);
    const float hiv = __int_as_float(g_dmax_bits);
    const float center = 0.5f * (lov + hiv);
    const float half   = fmaxf(0.5f * (hiv - lov), 1e-6f);

    if (blockIdx.x == 0) {
        // ---- compute C[32][32]: node grid + table-driven separable DCT ----
        __shared__ float cosT[128];             // cos(pi*k/64)
        __shared__ float sH[NC][NC + 1];
        __shared__ float sD[NC][NC + 1];
        const int t = threadIdx.x;
        if (t < 128) cosT[t] = cospif(t / 64.0f);
        __syncthreads();

        const float lsv = ls[0];
        const float invl2 = 1.0f / (lsv * lsv);

        #pragma unroll
        for (int e = t; e < NC * NC; e += 256) {
            int i = e >> 5, j = e & 31;
            float xi = center + half * cosT[2 * i + 1];   // cos(pi(i+.5)/32)
            float yj = center + half * cosT[2 * j + 1];
            float diff = xi - yj;
            float t2 = diff * diff * invl2;
            sH[i][j] = (invl2 - t2 * invl2) * expf(-0.5f * t2);
        }
        __syncthreads();
        #pragma unroll
        for (int e = t; e < NC * NC; e += 256) {
            int m = e >> 5, j = e & 31;
            float s = 0.0f;
            #pragma unroll
            for (int i = 0; i < NC; i++)
                s = fmaf(sH[i][j], cosT[(m * (2 * i + 1)) & 127], s);
            sD[m][j] = s;
        }
        __syncthreads();
        #pragma unroll
        for (int e = t; e < NC * NC; e += 256) {
            int m = e >> 5, n = e & 31;
            float s = 0.0f;
            #pragma unroll
            for (int j = 0; j < NC; j++)
                s = fmaf(sD[m][j], cosT[(n * (2 * j + 1)) & 127], s);
            float gm = (m ? 2.0f : 1.0f) * (n ? 2.0f : 1.0f) / (float)(NC * NC);
            g_C[m * NC + n] = s * gm;
        }
        return;
    }

    // ---- feature scatter: one warp per pair, lane = order m ----
    const int lane = threadIdx.x & 31;
    const int w = (blockIdx.x - 1) * 8 + (threadIdx.x >> 5);

    if (w < n1) {
        const int p = w;
        float s = (d1[p] - center) / half;
        s = fminf(1.0f, fmaxf(-1.0f, s));
        float th = acosf(s);
        float T = __cosf(lane * th);
        float ux = u1[3 * p], uy = u1[3 * p + 1], uz = u1[3 * p + 2];
        int base = i1[p] * (3 * NC) + lane;
        atomicAdd(&g_F1[base],           ux * T);
        atomicAdd(&g_F1[base + NC],      uy * T);
        atomicAdd(&g_F1[base + 2 * NC],  uz * T);
    } else if (w < n1 + n2) {
        const int q = w - n1;
        float s = (d2[q] - center) / half;
        s = fminf(1.0f, fmaxf(-1.0f, s));
        float th = acosf(s);
        float T = __cosf(lane * th);
        float ux = u2[3 * q], uy = u2[3 * q + 1], uz = u2[3 * q + 2];
        int base = i2[q] * (3 * NC) + lane;
        atomicAdd(&g_F2[base],           ux * T);
        atomicAdd(&g_F2[base + NC],      uy * T);
        atomicAdd(&g_F2[base + 2 * NC],  uz * T);
    }
}

// ------------------------------------------------------------------ GEMM + fold
// out[I][J] = sum_k F1[I][k] * (sum_n C[k][n] F2[J][n]).
// 128x64 tile, 256 threads, 4x8 per thread. ~2 blocks/SM at grid 288.
__global__ void __launch_bounds__(256) k_gemm(float* __restrict__ out,
                                              int nrows, int ncols) {
    __shared__ float As[NC * LDA];       // [k][row 0..127]
    __shared__ float Bs[NC * LDB];       // fold temp [row][32] then [k][row 0..63]
    __shared__ float sC[NC][NC + 1];

    const int t  = threadIdx.x;
    const int Ibase = blockIdx.y * TSI;
    const int Jbase = blockIdx.x * TSJ;

    // --- stage A (k-major), F2 (row-major temp in Bs), C ---
    {
        const int row0 = t >> 5, k = t & 31;     // row0 0..7, coalesced LDG
        #pragma unroll
        for (int r = 0; r < 16; r++)
            As[k * LDA + row0 + r * 8] = g_F1[(Ibase + row0 + r * 8) * NC + k];
        #pragma unroll
        for (int r = 0; r < 8; r++)
            Bs[(row0 + r * 8) * NC + k] = g_F2[(Jbase + row0 + r * 8) * NC + k];
        #pragma unroll
        for (int e = t; e < NC * NC; e += 256) sC[e >> 5][e & 31] = g_C[e];
    }
    __syncthreads();

    // --- fold: Bs[k][row] = sum_n C[k][n] * F2[row][n] ---
    float hold[8];
    {
        const int k = t & 31, row0 = t >> 5;
        float cr[NC];
        #pragma unroll
        for (int n = 0; n < NC; n++) cr[n] = sC[k][n];   // stride-33, conflict-free
        #pragma unroll
        for (int r = 0; r < 8; r++) {
            const float* f2 = &Bs[(row0 + r * 8) * NC];
            float s = 0.0f;
            #pragma unroll
            for (int n4 = 0; n4 < NC; n4 += 4) {
                float4 v = *(const float4*)&f2[n4];
                s = fmaf(cr[n4],     v.x, s);
                s = fmaf(cr[n4 + 1], v.y, s);
                s = fmaf(cr[n4 + 2], v.z, s);
                s = fmaf(cr[n4 + 3], v.w, s);
            }
            hold[r] = s;
        }
    }
    __syncthreads();
    {
        const int k = t & 31, row0 = t >> 5;
        #pragma unroll
        for (int r = 0; r < 8; r++)
            Bs[k * LDB + row0 + r * 8] = hold[r];
    }
    __syncthreads();

    // --- main: 4x8 register tile over K=32 ---
    const int tx = t & 7, ty = t >> 3;           // tx: 8 col-groups, ty: 32 row-groups
    float acc[4][8] = {};
    #pragma unroll
    for (int k = 0; k < NC; k++) {
        float4 a  = *(const float4*)&As[k * LDA + ty * 4];
        float4 b0 = *(const float4*)&Bs[k * LDB + tx * 8];
        float4 b1 = *(const float4*)&Bs[k * LDB + tx * 8 + 4];
        float av[4] = {a.x, a.y, a.z, a.w};
        float bv[8] = {b0.x, b0.y, b0.z, b0.w, b1.x, b1.y, b1.z, b1.w};
        #pragma unroll
        for (int i = 0; i < 4; i++)
            #pragma unroll
            for (int j = 0; j < 8; j++)
                acc[i][j] = fmaf(av[i], bv[j], acc[i][j]);
    }

    // --- write out ---
    #pragma unroll
    for (int i = 0; i < 4; i++) {
        int I = Ibase + ty * 4 + i;
        if (I >= nrows) break;
        float* orow = out + (size_t)I * ncols;
        #pragma unroll
        for (int j4 = 0; j4 < 8; j4 += 4) {
            int J = Jbase + tx * 8 + j4;
            if (J + 3 < ncols) {
                *(float4*)&orow[J] = make_float4(acc[i][j4], acc[i][j4 + 1],
                                                 acc[i][j4 + 2], acc[i][j4 + 3]);
            } else {
                #pragma unroll
                for (int j = 0; j < 4; j++)
                    if (J + j < ncols) orow[J + j] = acc[i][j4 + j];
            }
        }
    }
}

// ------------------------------------------------------------------ launch
extern "C" void kernel_launch(void* const* d_in, const int* in_sizes, int n_in,
                              void* d_out, int out_size) {
    const float* d1 = (const float*)d_in[0];
    const float* u1 = (const float*)d_in[1];
    const float* d2 = (const float*)d_in[2];
    const float* u2 = (const float*)d_in[3];
    const float* ls = (const float*)d_in[4];
    const int*   i1 = (const int*)d_in[5];
    const int*   i2 = (const int*)d_in[6];
    float* out = (float*)d_out;

    int n1 = in_sizes[0];
    int n2 = in_sizes[2];
    int side = (int)(sqrt((double)out_size) + 0.5);
    int nrows = side, ncols = side;

    // zero exactly the rows any tile can touch (side rounded up to TSI)
    int rows_pad = ((side + TSI - 1) / TSI) * TSI;
    if (rows_pad > ROWCAP) rows_pad = ROWCAP;
    int nquads = (rows_pad * NC) / 4;
    k_zero<<<(nquads + 255) / 256, 256>>>(d1, d2, n1, n2, nquads);

    int warps = n1 + n2;
    int featb = 1 + (warps + 7) / 8;
    k_feat<<<featb, 256>>>(d1, u1, d2, u2, ls, i1, i2, n1, n2);

    dim3 grid((ncols + TSJ - 1) / TSJ, (nrows + TSI - 1) / TSI);
    k_gemm<<<grid, 256>>>(out, nrows, ncols);
}